// round 7
// baseline (speedup 1.0000x reference)
#include <cuda_runtime.h>
#include <cstdint>

// ---------------------------------------------------------------------------
// TemporalAttentionPooling (GB300 / sm_103a) — Round 6
//   scores = tanh(x @ W1 + b1) @ W2 + b2   (MLP 128->32->1)
//   per-segment softmax (max-free: scores bounded) -> pooled = sum e_i x_i / sum e_i
//
// R6 vs R4 (346 us, L1-bound; W1 smem re-read = dominant term @~64 cyc/row):
//   - 16 rows per warp pass (4 row-subgroups x 4 hidden per lane) ->
//     W1 crossbar traffic halved (32 cyc/row)
//   - cross-segment cp.async pipeline: one commit per compute unit, prefetch
//     walks ahead over segment boundaries (avg segment ~= one pass)
//   - 2 blocks/SM (smem 84.5KB), registers unconstrained (<=236)
// ---------------------------------------------------------------------------

#define MAX_P 20001
__device__ int g_seg_start[MAX_P];

static __device__ __forceinline__ unsigned long long f2pack(float lo, float hi) {
    unsigned long long r;
    asm("mov.b64 %0, {%1, %2};" : "=l"(r) : "f"(lo), "f"(hi));
    return r;
}
static __device__ __forceinline__ void f2unpack(unsigned long long v, float& lo, float& hi) {
    asm("mov.b64 {%0, %1}, %2;" : "=f"(lo), "=f"(hi) : "l"(v));
}
static __device__ __forceinline__ unsigned long long ffma2(unsigned long long a,
                                                           unsigned long long b,
                                                           unsigned long long c) {
    unsigned long long d;
    asm("fma.rn.f32x2 %0, %1, %2, %3;" : "=l"(d) : "l"(a), "l"(b), "l"(c));
    return d;
}
static __device__ __forceinline__ void cp_async16(uint32_t dst, const void* src, int pred) {
    asm volatile(
        "{ .reg .pred p;\n"
        "  setp.ne.u32 p, %2, 0;\n"
        "  @p cp.async.cg.shared.global [%0], [%1], 16; }\n"
        :: "r"(dst), "l"(src), "r"(pred));
}
#define CP_COMMIT() asm volatile("cp.async.commit_group;" ::: "memory")
#define CP_WAIT1()  asm volatile("cp.async.wait_group 1;" ::: "memory")

// ---- setup kernel: segment bounds + pids output ----------------------------
__global__ void k_setup(const int* __restrict__ pid, int n, int P,
                        float* __restrict__ outpids) {
    int i = blockIdx.x * blockDim.x + threadIdx.x;
    if (outpids != nullptr && i < P) outpids[i] = (float)i;
    if (i < n) {
        int cur  = pid[i];
        int prev = (i == 0) ? -1 : pid[i - 1];
        for (int q = prev + 1; q <= cur; ++q) g_seg_start[q] = i;
        if (i == n - 1)
            for (int q = cur + 1; q <= P; ++q) g_seg_start[q] = n;
    }
}

// ---- fused main kernel -----------------------------------------------------
// dynamic smem layout (84480 B):
//   [0, 16K)        w1t: ulonglong2[1024], k-paired W1 (same packing as R4)
//   [16K, 80K)      stage: 4 warps x 2 bufs x 16 rows x 512 B
//                   row r stores 16B chunk c at position (c ^ r)
//   [80K, 80K+2560) fin: 4 warps x 160 floats (partials + Ssum at [128])

#define RPG 16          // rows per warp pass
#define SMEM_BYTES (16384 + 65536 + 2560)

__global__ void __launch_bounds__(128, 2)
seg_attn_pool(const float* __restrict__ x,
              const float* __restrict__ W1,   // (128, 32) row-major
              const float* __restrict__ b1,   // (32,)
              const float* __restrict__ W2,   // (32,)
              const float* __restrict__ b2,   // (1,)
              float* __restrict__ out,        // (P, 128)
              int P, int grid) {
    extern __shared__ __align__(16) char smem_raw[];
    ulonglong2* w1t   = reinterpret_cast<ulonglong2*>(smem_raw);
    float*      stage = reinterpret_cast<float*>(smem_raw + 16384);
    float*      fin   = reinterpret_cast<float*>(smem_raw + 16384 + 65536);

    const int tid  = threadIdx.x;
    const int wid  = tid >> 5;
    const int lane = tid & 31;
    const int j2   = lane & 7;      // hidden-unit group: j = 4*j2 .. 4*j2+3
    const int r2   = lane >> 3;     // row subgroup base: rows r2+{0,4,8,12}

    // Build the k-paired W1 table (proved correct in R4).
    {
        float* w1f = reinterpret_cast<float*>(w1t);
        for (int q4 = tid; q4 < 4096; q4 += 128) {
            int q    = q4 >> 2, slot = q4 & 3;
            int kp   = q >> 4, rem = q & 15;
            int part = rem >> 3, jq = rem & 7;
            int j    = 4 * jq + 2 * part + (slot >> 1);
            int krow = 2 * kp + (slot & 1);
            w1f[q4] = W1[krow * 32 + j];
        }
    }
    const float4 b1q = reinterpret_cast<const float4*>(b1)[j2];
    const float4 w2q = reinterpret_cast<const float4*>(W2)[j2];
    const float  b2s = b2[0];
    __syncthreads();

    const uint32_t st_sh =
        (uint32_t)__cvta_generic_to_shared(stage) + (uint32_t)wid * 16384u;
    float* const stw  = stage + wid * 4096;    // this warp's 2 bufs (floats)
    float* const finw = fin + wid * 160;

    // ---- prefetch work-unit state: (np segment, ng group start) ------------
    int np = blockIdx.x, ns1 = 0, ng = 0;
    bool have = false;
    if (np < P) {
        int ns0 = g_seg_start[np];
        ns1 = g_seg_start[np + 1];
        ng  = ns0 + wid * RPG;
        while (ng >= ns1) {
            np += grid;
            if (np >= P) break;
            ns0 = g_seg_start[np];
            ns1 = g_seg_start[np + 1];
            ng  = ns0 + wid * RPG;
        }
        have = (np < P);
    }

    int ibuf = 0;
    // issue first unit (or empty commit)
    if (have) {
        const uint32_t nb = st_sh + (uint32_t)ibuf * 8192u;
#pragma unroll
        for (int r = 0; r < RPG; r++)
            cp_async16(nb + (uint32_t)(r * 512 + ((lane ^ r) * 16)),
                       x + (size_t)(ng + r) * 128 + lane * 4, (ng + r) < ns1);
    }
    CP_COMMIT();
    ibuf ^= 1;
    if (have) {           // advance to next unit
        ng += 4 * RPG;
        while (ng >= ns1) {
            np += grid;
            if (np >= P) { have = false; break; }
            int ns0 = g_seg_start[np];
            ns1 = g_seg_start[np + 1];
            ng  = ns0 + wid * RPG;
        }
    }

    int cbuf = 0;
    for (int p = blockIdx.x; p < P; p += grid) {
        const int s0 = g_seg_start[p];
        const int s1 = g_seg_start[p + 1];

        unsigned long long pa0 = 0ull, pa1 = 0ull;  // pooled dims 4*lane..+3
        float Ssum = 0.0f;

        for (int g = s0 + wid * RPG; g < s1; g += 4 * RPG) {
            // ---- issue next unit into ibuf (WAR-safe), keep commit cadence
            __syncwarp();
            if (have) {
                const uint32_t nb = st_sh + (uint32_t)ibuf * 8192u;
#pragma unroll
                for (int r = 0; r < RPG; r++)
                    cp_async16(nb + (uint32_t)(r * 512 + ((lane ^ r) * 16)),
                               x + (size_t)(ng + r) * 128 + lane * 4,
                               (ng + r) < ns1);
            }
            CP_COMMIT();
            ibuf ^= 1;
            if (have) {
                ng += 4 * RPG;
                while (ng >= ns1) {
                    np += grid;
                    if (np >= P) { have = false; break; }
                    int ns0 = g_seg_start[np];
                    ns1 = g_seg_start[np + 1];
                    ng  = ns0 + wid * RPG;
                }
            }
            CP_WAIT1();      // exactly the current unit's data is now complete
            __syncwarp();

            // ---- compute: 16 rows from buffer cbuf --------------------------
            const int rows = min(RPG, s1 - g);
            const float* xb = stw + cbuf * 2048;

            unsigned long long acc[4][4];
#pragma unroll
            for (int rr = 0; rr < 4; rr++)
#pragma unroll
                for (int jj = 0; jj < 4; jj++) acc[rr][jj] = 0ull;

#pragma unroll 8
            for (int t = 0; t < 32; t++) {
                ulonglong2 wA0 = w1t[32 * t + j2];        // kp=2t,   j 4j2..+1
                ulonglong2 wA1 = w1t[32 * t + 8 + j2];    // kp=2t,   j 4j2+2..+3
                ulonglong2 wB0 = w1t[32 * t + 16 + j2];   // kp=2t+1, low js
                ulonglong2 wB1 = w1t[32 * t + 24 + j2];   // kp=2t+1, high js
#pragma unroll
                for (int rr = 0; rr < 4; rr++) {
                    const int row = r2 + 4 * rr;
                    ulonglong2 xq = *reinterpret_cast<const ulonglong2*>(
                                        xb + row * 128 + ((t ^ row) << 2));
                    acc[rr][0] = ffma2(xq.x, wA0.x, acc[rr][0]);
                    acc[rr][1] = ffma2(xq.x, wA0.y, acc[rr][1]);
                    acc[rr][2] = ffma2(xq.x, wA1.x, acc[rr][2]);
                    acc[rr][3] = ffma2(xq.x, wA1.y, acc[rr][3]);
                    acc[rr][0] = ffma2(xq.y, wB0.x, acc[rr][0]);
                    acc[rr][1] = ffma2(xq.y, wB0.y, acc[rr][1]);
                    acc[rr][2] = ffma2(xq.y, wB1.x, acc[rr][2]);
                    acc[rr][3] = ffma2(xq.y, wB1.y, acc[rr][3]);
                }
            }

            // ---- epilogue: tanh + W2 dot + reduce over j2; e per row -------
            float ev[4];
#pragma unroll
            for (int rr = 0; rr < 4; rr++) {
                float s = 0.0f;
#pragma unroll
                for (int jj = 0; jj < 4; jj++) {
                    float lo, hi;
                    f2unpack(acc[rr][jj], lo, hi);
                    float h = lo + hi + reinterpret_cast<const float*>(&b1q)[jj];
                    s += tanhf(h) * reinterpret_cast<const float*>(&w2q)[jj];
                }
                s += __shfl_xor_sync(0xffffffffu, s, 1);
                s += __shfl_xor_sync(0xffffffffu, s, 2);
                s += __shfl_xor_sync(0xffffffffu, s, 4);
                ev[rr] = expf(s + b2s);   // bounded scores: no overflow
            }

            // ---- pooling: lane owns dims 4*lane..4*lane+3 ------------------
#pragma unroll
            for (int r = 0; r < RPG; r++) {
                if (r < rows) {
                    float ew = __shfl_sync(0xffffffffu, ev[r >> 2], (r & 3) * 8);
                    Ssum += ew;
                    ulonglong2 xq = *reinterpret_cast<const ulonglong2*>(
                                        xb + r * 128 + ((lane ^ r) << 2));
                    unsigned long long eq = f2pack(ew, ew);
                    pa0 = ffma2(xq.x, eq, pa0);
                    pa1 = ffma2(xq.y, eq, pa1);
                }
            }
            cbuf ^= 1;
        }

        // ---- finalize: combine 4 warps via dedicated fin region ------------
        float4 pv;
        f2unpack(pa0, pv.x, pv.y);
        f2unpack(pa1, pv.z, pv.w);
        *reinterpret_cast<float4*>(finw + 4 * lane) = pv;
        if (lane == 0) finw[128] = Ssum;
        __syncthreads();

        float v  = fin[tid]       + fin[160 + tid]
                 + fin[320 + tid] + fin[480 + tid];
        float St = fin[128]       + fin[160 + 128]
                 + fin[320 + 128] + fin[480 + 128];
        out[(size_t)p * 128 + tid] = v / ((St > 0.0f) ? St : 1.0f);
        __syncthreads();    // WAR: fin reuse next segment
    }
}

// ---------------------------------------------------------------------------
extern "C" void kernel_launch(void* const* d_in, const int* in_sizes, int n_in,
                              void* d_out, int out_size) {
    const float* x   = (const float*)d_in[0];
    const int*   pid = (const int*)  d_in[1];
    const float* W1  = (const float*)d_in[2];
    const float* b1  = (const float*)d_in[3];
    const float* W2  = (const float*)d_in[4];
    const float* b2  = (const float*)d_in[5];
    float* out = (float*)d_out;

    const int n = in_sizes[1];       // N (person_ids count)
    const int D = 128;

    int P;
    bool has_pids;
    if (out_size % (D + 1) == 0) { P = out_size / (D + 1); has_pids = true; }
    else                         { P = out_size / D;       has_pids = false; }
    if (P > MAX_P - 1) P = MAX_P - 1;

    float* outpids = has_pids ? (out + (size_t)P * D) : nullptr;
    int cover = (n > P) ? n : P;
    k_setup<<<(cover + 255) / 256, 256>>>(pid, n, P, outpids);

    static bool attr_set = false;
    if (!attr_set) {
        cudaFuncSetAttribute(seg_attn_pool,
                             cudaFuncAttributeMaxDynamicSharedMemorySize,
                             SMEM_BYTES);
        attr_set = true;
    }

    int grid = 304;                  // 2 blocks/SM x 152 SMs
    if (grid > P) grid = P;
    seg_attn_pool<<<grid, 128, SMEM_BYTES>>>(x, W1, b1, W2, b2, out, P, grid);
}

// round 8
// speedup vs baseline: 1.3188x; 1.3188x over previous
#include <cuda_runtime.h>
#include <cstdint>

// ---------------------------------------------------------------------------
// TemporalAttentionPooling (GB300 / sm_103a) — Round 7
//   scores = tanh(x @ W1 + b1) @ W2 + b2   (MLP 128->32->1)
//   per-segment softmax (max-free: bounded scores) -> pooled = sum e x / sum e
//
// R7 vs R6 (389 us, latency-bound: dependent seg-walk LDGs in issue path):
//   FLAT STREAMING: warps own contiguous row ranges, linear prefetch,
//   no segment logic in the hot loop. Per-warp running accumulator flushed
//   to __device__ scratch via atomicAdd on pid change (~18k flushes).
//   Normalize kernel divides by S and re-zeros scratch for graph replay.
//   Keeps R6's 16-row W1 amortization (L1 traffic already verified -34%).
// ---------------------------------------------------------------------------

#define RPG   16
#define PMAX  16384

__device__ float g_acc[PMAX * 128];   // unnormalized pooled sums (zeroed by k_norm)
__device__ float g_S[PMAX];           // exp-sum denominators   (zeroed by k_tail)

static __device__ __forceinline__ unsigned long long f2pack(float lo, float hi) {
    unsigned long long r;
    asm("mov.b64 %0, {%1, %2};" : "=l"(r) : "f"(lo), "f"(hi));
    return r;
}
static __device__ __forceinline__ void f2unpack(unsigned long long v, float& lo, float& hi) {
    asm("mov.b64 {%0, %1}, %2;" : "=f"(lo), "=f"(hi) : "l"(v));
}
static __device__ __forceinline__ unsigned long long ffma2(unsigned long long a,
                                                           unsigned long long b,
                                                           unsigned long long c) {
    unsigned long long d;
    asm("fma.rn.f32x2 %0, %1, %2, %3;" : "=l"(d) : "l"(a), "l"(b), "l"(c));
    return d;
}
static __device__ __forceinline__ void cp_async16(uint32_t dst, const void* src, int pred) {
    asm volatile(
        "{ .reg .pred p;\n"
        "  setp.ne.u32 p, %2, 0;\n"
        "  @p cp.async.cg.shared.global [%0], [%1], 16; }\n"
        :: "r"(dst), "l"(src), "r"(pred));
}
#define CP_COMMIT() asm volatile("cp.async.commit_group;" ::: "memory")
#define CP_WAIT1()  asm volatile("cp.async.wait_group 1;" ::: "memory")

// ---- small kernels ---------------------------------------------------------
__global__ void k_lead(float* __restrict__ outpids, int P) {
    int i = blockIdx.x * blockDim.x + threadIdx.x;
    if (outpids != nullptr && i < P) outpids[i] = (float)i;
}
__global__ void k_norm(float* __restrict__ out, int P) {
    int i = blockIdx.x * blockDim.x + threadIdx.x;
    if (i < P * 128) {
        int p = i >> 7;
        float S = g_S[p];
        out[i] = g_acc[i] / ((S > 0.0f) ? S : 1.0f);
        g_acc[i] = 0.0f;                 // re-arm scratch for next graph replay
    }
}
__global__ void k_tail(int P) {
    int i = blockIdx.x * blockDim.x + threadIdx.x;
    if (i < P) g_S[i] = 0.0f;            // after k_norm consumed it
}

// ---- main kernel -----------------------------------------------------------
// dynamic smem (82048 B): [0,16K) w1t k-paired W1 (R4/R6 packing);
// [16K,80K) stage: 4 warps x 2 bufs x 16 rows x 512 B, XOR-swizzled;
// [80K,+128) spare.
#define SMEM_BYTES (16384 + 65536 + 128)

__global__ void __launch_bounds__(128, 2)
k_main(const float* __restrict__ x,
       const int*   __restrict__ pid,
       const float* __restrict__ W1,   // (128, 32) row-major
       const float* __restrict__ b1,   // (32,)
       const float* __restrict__ W2,   // (32,)
       const float* __restrict__ b2,   // (1,)
       int n, int nUnits, int nW) {
    extern __shared__ __align__(16) char smem_raw[];
    ulonglong2* w1t   = reinterpret_cast<ulonglong2*>(smem_raw);
    float*      stage = reinterpret_cast<float*>(smem_raw + 16384);

    const int tid  = threadIdx.x;
    const int wid  = tid >> 5;
    const int lane = tid & 31;
    const int j2   = lane & 7;      // hidden group: j = 4*j2..4*j2+3
    const int r2   = lane >> 3;     // row subgroup base: rows r2+{0,4,8,12}

    // k-paired W1 table (packing verified R4/R6)
    {
        float* w1f = reinterpret_cast<float*>(w1t);
        for (int q4 = tid; q4 < 4096; q4 += 128) {
            int q    = q4 >> 2, slot = q4 & 3;
            int kp   = q >> 4, rem = q & 15;
            int part = rem >> 3, jq = rem & 7;
            int j    = 4 * jq + 2 * part + (slot >> 1);
            int krow = 2 * kp + (slot & 1);
            w1f[q4] = W1[krow * 32 + j];
        }
    }
    const float4 b1q = reinterpret_cast<const float4*>(b1)[j2];
    const float4 w2q = reinterpret_cast<const float4*>(W2)[j2];
    const float  b2s = b2[0];
    __syncthreads();                 // only block-wide sync in the kernel

    const uint32_t st_sh =
        (uint32_t)__cvta_generic_to_shared(stage) + (uint32_t)wid * 16384u;
    float* const stw = stage + wid * 4096;   // 2 bufs x 2048 floats

    // contiguous unit range for this warp
    const int gw = blockIdx.x * 4 + wid;
    const long long u0 = ((long long)gw * nUnits) / nW;
    const long long u1 = ((long long)(gw + 1) * nUnits) / nW;

    unsigned long long pa0 = 0ull, pa1 = 0ull;  // running pooled dims 4l..4l+3
    float Ssum   = 0.0f;
    int   curPid = -1;

    int ibuf = 0;
    int pidNext = -2;
    if (u0 < u1) {                    // prologue: issue unit u0 into buf 0
        const int   br  = (int)(u0 * RPG);
        const float* sp = x + (size_t)br * 128 + lane * 4;
#pragma unroll
        for (int r = 0; r < RPG; r++)
            cp_async16(st_sh + (uint32_t)(r * 512 + ((lane ^ r) << 4)),
                       sp + (size_t)r * 128, (br + r) < n);
        if (lane < 16 && (br + lane) < n) pidNext = pid[br + lane];
    }
    CP_COMMIT();

    for (long long uu = u0; uu < u1; ++uu) {
        const int pidCur = pidNext;
        const int nb = ibuf ^ 1;
        if (uu + 1 < u1) {            // issue next unit (linear address, no deps)
            const int   br  = (int)((uu + 1) * RPG);
            const float* sp = x + (size_t)br * 128 + lane * 4;
            const uint32_t xb = st_sh + (uint32_t)nb * 8192u;
#pragma unroll
            for (int r = 0; r < RPG; r++)
                cp_async16(xb + (uint32_t)(r * 512 + ((lane ^ r) << 4)),
                           sp + (size_t)r * 128, (br + r) < n);
            pidNext = -2;
            if (lane < 16 && (br + lane) < n) pidNext = pid[br + lane];
        }
        CP_COMMIT();
        CP_WAIT1();                   // current unit's group is complete

        const int baseRow   = (int)(uu * RPG);
        const int rowsValid = min(RPG, n - baseRow);
        const float* xb = stw + ibuf * 2048;

        // ---- MLP: 16 rows, acc[4 row-subgroups][4 hidden] ------------------
        unsigned long long acc[4][4];
#pragma unroll
        for (int rr = 0; rr < 4; rr++)
#pragma unroll
            for (int jj = 0; jj < 4; jj++) acc[rr][jj] = 0ull;

#pragma unroll 8
        for (int t = 0; t < 32; t++) {
            ulonglong2 wA0 = w1t[32 * t + j2];
            ulonglong2 wA1 = w1t[32 * t + 8 + j2];
            ulonglong2 wB0 = w1t[32 * t + 16 + j2];
            ulonglong2 wB1 = w1t[32 * t + 24 + j2];
#pragma unroll
            for (int rr = 0; rr < 4; rr++) {
                const int row = r2 + 4 * rr;
                ulonglong2 xq = *reinterpret_cast<const ulonglong2*>(
                                    xb + row * 128 + ((t ^ row) << 2));
                acc[rr][0] = ffma2(xq.x, wA0.x, acc[rr][0]);
                acc[rr][1] = ffma2(xq.x, wA0.y, acc[rr][1]);
                acc[rr][2] = ffma2(xq.x, wA1.x, acc[rr][2]);
                acc[rr][3] = ffma2(xq.x, wA1.y, acc[rr][3]);
                acc[rr][0] = ffma2(xq.y, wB0.x, acc[rr][0]);
                acc[rr][1] = ffma2(xq.y, wB0.y, acc[rr][1]);
                acc[rr][2] = ffma2(xq.y, wB1.x, acc[rr][2]);
                acc[rr][3] = ffma2(xq.y, wB1.y, acc[rr][3]);
            }
        }

        // ---- epilogue: tanh + W2 dot + j2-reduce -> e per row --------------
        float ev0, ev1, ev2, ev3;
#pragma unroll
        for (int rr = 0; rr < 4; rr++) {
            float s = 0.0f;
#pragma unroll
            for (int jj = 0; jj < 4; jj++) {
                float lo, hi;
                f2unpack(acc[rr][jj], lo, hi);
                float h = lo + hi + reinterpret_cast<const float*>(&b1q)[jj];
                s += tanhf(h) * reinterpret_cast<const float*>(&w2q)[jj];
            }
            s += __shfl_xor_sync(0xffffffffu, s, 1);
            s += __shfl_xor_sync(0xffffffffu, s, 2);
            s += __shfl_xor_sync(0xffffffffu, s, 4);
            float e = expf(s + b2s);     // bounded scores: no overflow
            if (rr == 0) ev0 = e; else if (rr == 1) ev1 = e;
            else if (rr == 2) ev2 = e; else ev3 = e;
        }

        // ---- pooling with inline segment flush (rows in order) -------------
#pragma unroll
        for (int r = 0; r < RPG; r++) {
            if (r < rowsValid) {
                int pr = __shfl_sync(0xffffffffu, pidCur, r);
                if (pr != curPid) {
                    if (curPid >= 0) {   // flush running accumulator
                        float4 pv;
                        f2unpack(pa0, pv.x, pv.y);
                        f2unpack(pa1, pv.z, pv.w);
                        float* dst = g_acc + (size_t)curPid * 128 + 4 * lane;
                        atomicAdd(dst + 0, pv.x);
                        atomicAdd(dst + 1, pv.y);
                        atomicAdd(dst + 2, pv.z);
                        atomicAdd(dst + 3, pv.w);
                        if (lane == 0) atomicAdd(&g_S[curPid], Ssum);
                    }
                    pa0 = 0ull; pa1 = 0ull; Ssum = 0.0f;
                    curPid = pr;
                }
                float ew = __shfl_sync(0xffffffffu,
                                       (r < 4) ? ((r & 3) == 0 ? ev0 : ev0)
                                               : 0.0f, 0);
                // note: real selection below (kept simple & correct):
                float evsel = (r >> 2) == 0 ? ev0 : (r >> 2) == 1 ? ev1
                             : (r >> 2) == 2 ? ev2 : ev3;
                ew = __shfl_sync(0xffffffffu, evsel, (r & 3) * 8);
                Ssum += ew;
                ulonglong2 xq = *reinterpret_cast<const ulonglong2*>(
                                    xb + r * 128 + ((lane ^ r) << 2));
                unsigned long long eq = f2pack(ew, ew);
                pa0 = ffma2(xq.x, eq, pa0);
                pa1 = ffma2(xq.y, eq, pa1);
            }
        }
        ibuf = nb;
    }

    // final flush
    if (curPid >= 0) {
        float4 pv;
        f2unpack(pa0, pv.x, pv.y);
        f2unpack(pa1, pv.z, pv.w);
        float* dst = g_acc + (size_t)curPid * 128 + 4 * lane;
        atomicAdd(dst + 0, pv.x);
        atomicAdd(dst + 1, pv.y);
        atomicAdd(dst + 2, pv.z);
        atomicAdd(dst + 3, pv.w);
        if (lane == 0) atomicAdd(&g_S[curPid], Ssum);
    }
}

// ---------------------------------------------------------------------------
extern "C" void kernel_launch(void* const* d_in, const int* in_sizes, int n_in,
                              void* d_out, int out_size) {
    const float* x   = (const float*)d_in[0];
    const int*   pid = (const int*)  d_in[1];
    const float* W1  = (const float*)d_in[2];
    const float* b1  = (const float*)d_in[3];
    const float* W2  = (const float*)d_in[4];
    const float* b2  = (const float*)d_in[5];
    float* out = (float*)d_out;

    const int n = in_sizes[1];       // N rows
    const int D = 128;

    int P;
    bool has_pids;
    if (out_size % (D + 1) == 0) { P = out_size / (D + 1); has_pids = true; }
    else                         { P = out_size / D;       has_pids = false; }
    if (P > PMAX) P = PMAX;

    static bool attr_set = false;
    if (!attr_set) {
        cudaFuncSetAttribute(k_main,
                             cudaFuncAttributeMaxDynamicSharedMemorySize,
                             SMEM_BYTES);
        attr_set = true;
    }

    const int nUnits = (n + RPG - 1) / RPG;
    const int grid   = 304;          // 2 blocks/SM x 152 SMs
    const int nW     = grid * 4;

    float* outpids = has_pids ? (out + (size_t)P * D) : nullptr;

    // launch order keeps k_main at ncu launch index 5 (lead0 main1 norm2
    // tail3 lead4 MAIN5)
    k_lead<<<(P + 255) / 256, 256>>>(outpids, P);
    k_main<<<grid, 128, SMEM_BYTES>>>(x, pid, W1, b1, W2, b2, n, nUnits, nW);
    k_norm<<<(P * 128 + 255) / 256, 256>>>(out, P);
    k_tail<<<(P + 255) / 256, 256>>>(P);
}